// round 6
// baseline (speedup 1.0000x reference)
#include <cuda_runtime.h>
#include <math.h>

#define BB 64
#define NN 16800
#define CC 21
#define TPB 256
#define NBLK 66          // ceil(16800/256)
#define HBINS 2048
#define FP32_EPS 1.1920928955078125e-07f

// ---------------- scratch (device globals; no allocation) ----------------
__device__ float    d_neg [BB * NN];      // labels_neg (0 for positives, ce otherwise)
__device__ unsigned d_hist[BB * HBINS];   // stage-0 histogram (bits[31:21]); zero-init,
                                          // re-zeroed by k_select each run
__device__ float d_psl1[BB * NBLK];
__device__ float d_pce [BB * NBLK];
__device__ int   d_ppos[BB * NBLK];
__device__ float d_res [BB * 3];
__device__ int   d_done;                  // ticket for fused final reduction (self-resetting)

__device__ __forceinline__ float smooth_l1(float d) {
    float a = fabsf(d);
    return (a < 1.f) ? (0.5f * a * a) : (a - 0.5f);
}

// ---------------- main: per-anchor sl1 + ce; partials; global coarse histogram ----------------
__global__ void __launch_bounds__(TPB, 8)
k_main(const float4* __restrict__ pb,
       const float4* __restrict__ gb,
       const float4* __restrict__ pl4,
       const int*    __restrict__ gl,
       const float4* __restrict__ anc)
{
    __shared__ float s_lab[TPB * CC];
    __shared__ float rs[8], rc[8];
    __shared__ int   rp[8];

    const int b    = blockIdx.y;
    const int base = blockIdx.x * TPB;
    const int tid  = threadIdx.x;
    const int n    = base + tid;
    const int cnt  = min(TPB, NN - base);

    {
        const float4* src = pl4 + ((size_t)b * NN + base) * CC / 4;
        float4* dst = (float4*)s_lab;
        const int tot4 = (cnt * CC) >> 2;
        for (int i = tid; i < tot4; i += TPB) dst[i] = src[i];
    }
    __syncthreads();

    float sl1 = 0.f, ce = 0.f;
    int pos = 0;
    if (tid < cnt) {
        float4 a = anc[n];
        float4 g = gb[b * NN + n];
        float4 p = pb[b * NN + n];
        float t0 = 10.f * (g.x - a.x) / a.z;
        float t1 = 10.f * (g.y - a.y) / a.w;
        float t2 = 5.f * __logf(g.z / a.z);
        float t3 = 5.f * __logf(g.w / a.w);
        sl1 = smooth_l1(p.x - t0) + smooth_l1(p.y - t1)
            + smooth_l1(p.z - t2) + smooth_l1(p.w - t3);

        const float* x = s_lab + tid * CC;   // stride 21, conflict-free
        float s = 0.f;
        #pragma unroll
        for (int j = 0; j < CC; j++) s += __expf(x[j]);
        int lab = gl[b * NN + n];
        ce = __logf(s) - x[lab];
        pos = (lab > 0);

        float neg = pos ? 0.f : ce;
        d_neg[b * NN + n] = neg;
        // coarse histogram via L2 REDG (no-return): hot addresses spread over LTS
        atomicAdd(&d_hist[b * HBINS + (__float_as_uint(neg) >> 21)], 1u);
    }

    float vsl = pos ? sl1 : 0.f;
    float vce = pos ? ce  : 0.f;
    #pragma unroll
    for (int o = 16; o; o >>= 1) {
        vsl += __shfl_down_sync(0xFFFFFFFFu, vsl, o);
        vce += __shfl_down_sync(0xFFFFFFFFu, vce, o);
    }
    int wp = __popc(__ballot_sync(0xFFFFFFFFu, pos));
    int w = tid >> 5, l = tid & 31;
    if (l == 0) { rs[w] = vsl; rc[w] = vce; rp[w] = wp; }
    __syncthreads();
    if (tid == 0) {
        float A = 0.f, Cc = 0.f; int P = 0;
        #pragma unroll
        for (int i = 0; i < 8; i++) { A += rs[i]; Cc += rc[i]; P += rp[i]; }
        const int idx = b * NBLK + blockIdx.x;
        d_psl1[idx] = A;
        d_pce [idx] = Cc;
        d_ppos[idx] = P;
    }
}

// ---------------- select: one block per batch ----------------
#define SEL_T 1024
// SMEM: buf[NN] u32 + hist[2048] + gsum[256]
#define SEL_SMEM (NN * 4 + HBINS * 4 + 256 * 4)

__device__ __forceinline__ void warp_locate(const unsigned* hist, const unsigned* gsum,
                                            int gper, int k,
                                            unsigned* o_sel, unsigned* o_krem) {
    const int lane = threadIdx.x;  // caller guarantees tid < 32
    unsigned g[8];
    unsigned p = 0;
    #pragma unroll
    for (int j = 0; j < 8; j++) { g[j] = gsum[lane * 8 + j]; p += g[j]; }
    unsigned sfx = p;
    #pragma unroll
    for (int o = 1; o < 32; o <<= 1) {
        unsigned v = __shfl_down_sync(0xFFFFFFFFu, sfx, o);
        if (lane + o < 32) sfx += v;
    }
    unsigned above = sfx - p;
    if (above < (unsigned)k && sfx >= (unsigned)k) {
        unsigned cum = above;
        #pragma unroll
        for (int j = 7; j >= 0; j--) {
            unsigned gj = g[j];
            if (cum + gj >= (unsigned)k) {
                const int bbase = (lane * 8 + j) * gper;
                for (int q = gper - 1; q >= 0; q--) {
                    unsigned h = hist[bbase + q];
                    if (cum + h >= (unsigned)k) {
                        *o_sel  = (unsigned)(bbase + q);
                        *o_krem = (unsigned)k - cum;
                        return;
                    }
                    cum += h;
                }
            }
            cum += gj;
        }
    }
}

__global__ void __launch_bounds__(SEL_T, 1) k_select(float* __restrict__ out) {
    extern __shared__ unsigned smu[];
    unsigned* buf  = smu;              // NN (boundary-bin candidates, any order)
    unsigned* hist = buf + NN;         // 2048
    unsigned* gsum = hist + HBINS;     // 256

    __shared__ float a66[NBLK], c66[NBLK];
    __shared__ int   p66[NBLK];
    __shared__ float red[32];
    __shared__ unsigned long long red64[32];
    __shared__ unsigned redc[32];
    __shared__ unsigned s_sel, s_krem;
    __shared__ int   s_k, s_pos, s_gcnt;
    __shared__ float s_lossb, s_cepos;
    __shared__ int   s_last;

    const int b    = blockIdx.x;
    const int tid  = threadIdx.x;
    const int lane = tid & 31;

    // phase A: load global hist into SMEM, zero it for next replay; stage partials
    for (int i = tid; i < HBINS; i += SEL_T) {
        hist[i] = d_hist[b * HBINS + i];
        d_hist[b * HBINS + i] = 0u;
    }
    if (tid < NBLK) {
        const int idx = b * NBLK + tid;
        a66[tid] = d_psl1[idx];
        c66[tid] = d_pce [idx];
        p66[tid] = d_ppos[idx];
    }
    if (tid == 0) s_gcnt = 0;
    __syncthreads();

    // gsum + partials reduce (warp 8)
    if (tid < 256) {
        unsigned t = 0;
        #pragma unroll
        for (int j = 0; j < 8; j++) t += hist[tid * 8 + j];
        gsum[tid] = t;
    }
    if (tid >= 256 && tid < 288) {
        const int l = tid - 256;
        float A  = a66[l] + a66[l + 32] + ((l < 2) ? a66[l + 64] : 0.f);
        float Cc = c66[l] + c66[l + 32] + ((l < 2) ? c66[l + 64] : 0.f);
        int   P  = p66[l] + p66[l + 32] + ((l < 2) ? p66[l + 64] : 0);
        #pragma unroll
        for (int o = 16; o; o >>= 1) {
            A  += __shfl_down_sync(0xFFFFFFFFu, A, o);
            Cc += __shfl_down_sync(0xFFFFFFFFu, Cc, o);
            P  += __shfl_down_sync(0xFFFFFFFFu, P, o);
        }
        if (l == 0) {
            s_lossb = A; s_cepos = Cc; s_pos = P;
            s_k = min(3 * P, NN);
        }
    }
    __syncthreads();

    const int k0 = s_k;
    unsigned tb = 0;
    int ties = 0;
    unsigned sel0 = 0;
    float acc = 0.f;                    // sum of values strictly above coarse bin
    unsigned long long msum = 0ull;     // in-bin mantissa sum (order-independent)
    unsigned csel = 0;                  // in-bin selected count

    if (k0 > 0) {
        if (tid < 32) warp_locate(hist, gsum, 8, k0, &s_sel, &s_krem);
        __syncthreads();
        sel0 = s_sel;
        int k = (int)s_krem;

        // phase B: ONE pass over d_neg (L2-resident): above-bin sum + compact boundary bin
        {
            const uint4* src = (const uint4*)(d_neg + b * NN);
            const int NIT = (NN / 4 + SEL_T - 1) / SEL_T;   // 5
            for (int it = 0; it < NIT; it++) {
                const int i = it * SEL_T + tid;
                const bool valid = (i < NN / 4);
                uint4 t = valid ? src[i] : make_uint4(0u, 0u, 0u, 0u);
                unsigned v[4] = {t.x, t.y, t.z, t.w};
                #pragma unroll
                for (int c = 0; c < 4; c++) {
                    const unsigned bits = v[c];
                    const unsigned bin  = bits >> 21;
                    if (valid && bin > sel0) acc += __uint_as_float(bits);
                    const bool pred = valid && (bin == sel0);
                    unsigned bal = __ballot_sync(0xFFFFFFFFu, pred);
                    if (bal) {
                        int base_ = 0;
                        if (lane == 0) base_ = atomicAdd(&s_gcnt, __popc(bal));
                        base_ = __shfl_sync(0xFFFFFFFFu, base_, 0);
                        if (pred) buf[base_ + __popc(bal & ((1u << lane) - 1))] = bits;
                    }
                }
            }
        }
        __syncthreads();
        const int gcnt = s_gcnt;

        // refine stage 1: bits[20:10] (mantissa bits -> well-spread atomics)
        for (int i = tid; i < HBINS; i += SEL_T) hist[i] = 0u;
        __syncthreads();
        for (int i = tid; i < gcnt; i += SEL_T)
            atomicAdd(&hist[(buf[i] >> 10) & 0x7FFu], 1u);
        __syncthreads();
        if (tid < 256) {
            unsigned t = 0;
            #pragma unroll
            for (int j = 0; j < 8; j++) t += hist[tid * 8 + j];
            gsum[tid] = t;
        }
        __syncthreads();
        if (tid < 32) warp_locate(hist, gsum, 8, k, &s_sel, &s_krem);
        __syncthreads();
        const unsigned sel1 = s_sel;
        k = (int)s_krem;

        // refine stage 2: bits[9:0]
        for (int i = tid; i < 1024; i += SEL_T) hist[i] = 0u;
        __syncthreads();
        for (int i = tid; i < gcnt; i += SEL_T) {
            unsigned bits = buf[i];
            if (((bits >> 10) & 0x7FFu) == sel1)
                atomicAdd(&hist[bits & 0x3FFu], 1u);
        }
        __syncthreads();
        if (tid < 256) {
            unsigned t = 0;
            #pragma unroll
            for (int j = 0; j < 4; j++) t += hist[tid * 4 + j];
            gsum[tid] = t;
        }
        __syncthreads();
        if (tid < 32) warp_locate(hist, gsum, 4, k, &s_sel, &s_krem);
        __syncthreads();

        tb   = (sel0 << 21) | (sel1 << 10) | s_sel;
        ties = (int)s_krem;

        // phase D: in-bin strictly-above sum in integer domain (order-independent:
        // all candidates share exponent+top-2-mantissa bits)
        for (int i = tid; i < gcnt; i += SEL_T) {
            unsigned bits = buf[i];
            if (bits > tb) { msum += (bits & 0x7FFFFFu); csel++; }
        }
    }

    // block reductions (acc float, msum u64, csel u32)
    #pragma unroll
    for (int o = 16; o; o >>= 1) {
        acc  += __shfl_down_sync(0xFFFFFFFFu, acc,  o);
        msum += __shfl_down_sync(0xFFFFFFFFu, msum, o);
        csel += __shfl_down_sync(0xFFFFFFFFu, csel, o);
    }
    const int w = tid >> 5;
    if (lane == 0) { red[w] = acc; red64[w] = msum; redc[w] = csel; }
    __syncthreads();
    if (tid == 0) {
        float ta = 0.f; unsigned long long tm = 0ull; unsigned tc = 0;
        #pragma unroll
        for (int i = 0; i < 32; i++) { ta += red[i]; tm += red64[i]; tc += redc[i]; }

        float negsum = 0.f;
        if (k0 > 0) {
            const unsigned e8 = (sel0 >> 2) & 0xFFu;
            if (e8) tm += (unsigned long long)tc << 23;      // implicit leading bit
            const int ex = (int)(e8 ? e8 : 1u) - 150;
            float in_sum = (float)ldexp((double)tm, ex);
            negsum = ta + in_sum + (float)ties * __uint_as_float(tb);
        }

        float lb = s_lossb;
        float ll = s_cepos + negsum;
        int   pn = s_pos;
        float nm = (pn > 0) ? 1.f : 0.f;
        float pf = fmaxf((float)pn, FP32_EPS);
        d_res[b * 3 + 0] = (lb + ll) * nm / pf;
        d_res[b * 3 + 1] = lb * nm / pf;
        d_res[b * 3 + 2] = ll * nm / pf;

        __threadfence();
        s_last = (atomicAdd(&d_done, 1) == BB - 1);
    }
    __syncthreads();

    // fused final reduction: last-finishing block reduces all 64 batch results
    if (s_last) {
        __threadfence();
        float lt = 0.f, vb = 0.f, vl = 0.f;
        if (tid < BB) {
            volatile float* r = d_res;
            lt = r[tid * 3 + 0];
            vb = r[tid * 3 + 1];
            vl = r[tid * 3 + 2];
        }
        if (tid < 64) {
            #pragma unroll
            for (int o = 16; o; o >>= 1) {
                lt += __shfl_down_sync(0xFFFFFFFFu, lt, o);
                vb += __shfl_down_sync(0xFFFFFFFFu, vb, o);
                vl += __shfl_down_sync(0xFFFFFFFFu, vl, o);
            }
            if ((tid & 31) == 0) {
                red[tid >> 5]       = lt;
                red[(tid >> 5) + 2] = vb;
                red[(tid >> 5) + 4] = vl;
            }
        }
        __syncthreads();
        if (tid == 0) {
            out[0] = (red[0] + red[1]) * (1.f / 64.f);
            out[1] = (red[2] + red[3]) * (1.f / 64.f);
            out[2] = (red[4] + red[5]) * (1.f / 64.f);
            d_done = 0;   // self-reset for next graph replay
        }
    }
}

// ---------------- launch ----------------
extern "C" void kernel_launch(void* const* d_in, const int* in_sizes, int n_in,
                              void* d_out, int out_size) {
    const float4* pb  = (const float4*)d_in[0];
    const float4* gb  = (const float4*)d_in[1];
    const float4* pl4 = (const float4*)d_in[2];
    const int*    gl  = (const int*)d_in[3];
    const float4* anc = (const float4*)d_in[4];
    float* out = (float*)d_out;

    static bool attr_set = false;
    if (!attr_set) {
        cudaFuncSetAttribute(k_select, cudaFuncAttributeMaxDynamicSharedMemorySize, SEL_SMEM);
        attr_set = true;
    }

    dim3 gBN(NBLK, BB);
    k_main<<<gBN, TPB>>>(pb, gb, pl4, gl, anc);
    k_select<<<BB, SEL_T, SEL_SMEM>>>(out);
}

// round 7
// speedup vs baseline: 1.2444x; 1.2444x over previous
#include <cuda_runtime.h>
#include <math.h>

#define BB 64
#define NN 16800
#define CC 21
#define TPB 256
#define NBLK 66          // ceil(16800/256)
#define HBINS 2048
#define FP32_EPS 1.1920928955078125e-07f

// ---------------- scratch (device globals; no allocation) ----------------
__device__ float d_neg [BB * NN];
__device__ float d_psl1[BB * NBLK];
__device__ float d_pce [BB * NBLK];
__device__ int   d_ppos[BB * NBLK];
__device__ float d_res [BB * 3];
__device__ int   d_done;                  // ticket for fused final reduction (self-resetting)

__device__ __forceinline__ float smooth_l1(float d) {
    float a = fabsf(d);
    return (a < 1.f) ? (0.5f * a * a) : (a - 0.5f);
}

// linear equal-width bin over [0,32): spreads ce population across ~300 bins
__device__ __forceinline__ unsigned lin_bin(float v) {
    return min(2047u, (unsigned)(v * 64.0f));
}

// ---------------- main: per-anchor sl1 + ce; per-block partials ----------------
__global__ void __launch_bounds__(TPB, 8)
k_main(const float4* __restrict__ pb,
       const float4* __restrict__ gb,
       const float4* __restrict__ pl4,
       const int*    __restrict__ gl,
       const float4* __restrict__ anc)
{
    __shared__ float s_lab[TPB * CC];
    __shared__ float rs[8], rc[8];
    __shared__ int   rp[8];

    const int b    = blockIdx.y;
    const int base = blockIdx.x * TPB;
    const int tid  = threadIdx.x;
    const int n    = base + tid;
    const int cnt  = min(TPB, NN - base);

    {
        const float4* src = pl4 + ((size_t)b * NN + base) * CC / 4;
        float4* dst = (float4*)s_lab;
        const int tot4 = (cnt * CC) >> 2;
        for (int i = tid; i < tot4; i += TPB) dst[i] = src[i];
    }
    __syncthreads();

    float sl1 = 0.f, ce = 0.f;
    int pos = 0;
    if (tid < cnt) {
        float4 a = anc[n];
        float4 g = gb[b * NN + n];
        float4 p = pb[b * NN + n];
        float t0 = 10.f * (g.x - a.x) / a.z;
        float t1 = 10.f * (g.y - a.y) / a.w;
        float t2 = 5.f * __logf(g.z / a.z);
        float t3 = 5.f * __logf(g.w / a.w);
        sl1 = smooth_l1(p.x - t0) + smooth_l1(p.y - t1)
            + smooth_l1(p.z - t2) + smooth_l1(p.w - t3);

        const float* x = s_lab + tid * CC;   // stride 21, conflict-free
        float s = 0.f;
        #pragma unroll
        for (int j = 0; j < CC; j++) s += __expf(x[j]);
        int lab = gl[b * NN + n];
        ce = __logf(s) - x[lab];
        pos = (lab > 0);

        d_neg[b * NN + n] = pos ? 0.f : ce;
    }

    float vsl = pos ? sl1 : 0.f;
    float vce = pos ? ce  : 0.f;
    #pragma unroll
    for (int o = 16; o; o >>= 1) {
        vsl += __shfl_down_sync(0xFFFFFFFFu, vsl, o);
        vce += __shfl_down_sync(0xFFFFFFFFu, vce, o);
    }
    int wp = __popc(__ballot_sync(0xFFFFFFFFu, pos));
    int w = tid >> 5, l = tid & 31;
    if (l == 0) { rs[w] = vsl; rc[w] = vce; rp[w] = wp; }
    __syncthreads();
    if (tid == 0) {
        float A = 0.f, Cc = 0.f; int P = 0;
        #pragma unroll
        for (int i = 0; i < 8; i++) { A += rs[i]; Cc += rc[i]; P += rp[i]; }
        const int idx = b * NBLK + blockIdx.x;
        d_psl1[idx] = A;
        d_pce [idx] = Cc;
        d_ppos[idx] = P;
    }
}

// ---------------- select: one block per batch ----------------
#define SEL_T 1024
// SMEM: vals[NN] + buf[NN] + hist[2048] + gsum[256]
#define SEL_SMEM (NN * 4 + NN * 4 + HBINS * 4 + 256 * 4)

// Warp 0: suffix-scan 256 group sums via shuffle, locate bin with k-th largest.
__device__ __forceinline__ void warp_locate(const unsigned* hist, const unsigned* gsum,
                                            int gper, int k,
                                            unsigned* o_sel, unsigned* o_krem) {
    const int lane = threadIdx.x;  // caller guarantees tid < 32
    unsigned g[8];
    unsigned p = 0;
    #pragma unroll
    for (int j = 0; j < 8; j++) { g[j] = gsum[lane * 8 + j]; p += g[j]; }
    unsigned sfx = p;
    #pragma unroll
    for (int o = 1; o < 32; o <<= 1) {
        unsigned v = __shfl_down_sync(0xFFFFFFFFu, sfx, o);
        if (lane + o < 32) sfx += v;
    }
    unsigned above = sfx - p;
    if (above < (unsigned)k && sfx >= (unsigned)k) {
        unsigned cum = above;
        #pragma unroll
        for (int j = 7; j >= 0; j--) {
            unsigned gj = g[j];
            if (cum + gj >= (unsigned)k) {
                const int bbase = (lane * 8 + j) * gper;
                for (int q = gper - 1; q >= 0; q--) {
                    unsigned h = hist[bbase + q];
                    if (cum + h >= (unsigned)k) {
                        *o_sel  = (unsigned)(bbase + q);
                        *o_krem = (unsigned)k - cum;
                        return;
                    }
                    cum += h;
                }
            }
            cum += gj;
        }
    }
}

__global__ void __launch_bounds__(SEL_T, 1) k_select(float* __restrict__ out) {
    extern __shared__ float sm[];
    float*    vals = sm;                       // NN floats
    unsigned* buf  = (unsigned*)(vals + NN);   // NN (boundary-bin candidates, any order;
                                               //     used ONLY for counting)
    unsigned* hist = buf + NN;                 // 2048
    unsigned* gsum = hist + HBINS;             // 256

    __shared__ float a66[NBLK], c66[NBLK];
    __shared__ int   p66[NBLK];
    __shared__ float red[32];
    __shared__ unsigned s_sel, s_krem;
    __shared__ int   s_k, s_pos, s_gcnt;
    __shared__ float s_lossb, s_cepos;
    __shared__ int   s_last;

    const int b    = blockIdx.x;
    const int tid  = threadIdx.x;
    const int lane = tid & 31;

    // phase A: zero hist; stage per-block partials
    for (int i = tid; i < HBINS; i += SEL_T) hist[i] = 0u;
    if (tid < NBLK) {
        const int idx = b * NBLK + tid;
        a66[tid] = d_psl1[idx];
        c66[tid] = d_pce [idx];
        p66[tid] = d_ppos[idx];
    }
    if (tid == 0) s_gcnt = 0;
    __syncthreads();

    // phase B: fused float4 load + LINEAR-bin histogram (spread -> low ATOMS conflicts)
    {
        const float4* src = (const float4*)(d_neg + b * NN);
        float4* v4 = (float4*)vals;
        for (int i = tid; i < NN / 4; i += SEL_T) {
            float4 t = src[i];
            v4[i] = t;
            atomicAdd(&hist[lin_bin(t.x)], 1u);
            atomicAdd(&hist[lin_bin(t.y)], 1u);
            atomicAdd(&hist[lin_bin(t.z)], 1u);
            atomicAdd(&hist[lin_bin(t.w)], 1u);
        }
    }
    __syncthreads();

    // phase C: gsum + partials reduce (warp 8)
    if (tid < 256) {
        unsigned t = 0;
        #pragma unroll
        for (int j = 0; j < 8; j++) t += hist[tid * 8 + j];
        gsum[tid] = t;
    }
    if (tid >= 256 && tid < 288) {
        const int l = tid - 256;
        float A  = a66[l] + a66[l + 32] + ((l < 2) ? a66[l + 64] : 0.f);
        float Cc = c66[l] + c66[l + 32] + ((l < 2) ? c66[l + 64] : 0.f);
        int   P  = p66[l] + p66[l + 32] + ((l < 2) ? p66[l + 64] : 0);
        #pragma unroll
        for (int o = 16; o; o >>= 1) {
            A  += __shfl_down_sync(0xFFFFFFFFu, A, o);
            Cc += __shfl_down_sync(0xFFFFFFFFu, Cc, o);
            P  += __shfl_down_sync(0xFFFFFFFFu, P, o);
        }
        if (l == 0) {
            s_lossb = A; s_cepos = Cc; s_pos = P;
            s_k = min(3 * P, NN);
        }
    }
    __syncthreads();

    const int k0 = s_k;
    unsigned tb = 0;
    int ties = 0;

    if (k0 > 0) {
        // stage-0 locate over linear bins
        if (tid < 32) warp_locate(hist, gsum, 8, k0, &s_sel, &s_krem);
        __syncthreads();
        const unsigned sel0 = s_sel;
        int k = (int)s_krem;

        // gather boundary-bin candidates (nondeterministic order; counting only)
        for (int i = tid; i < NN; i += SEL_T) {
            float v = vals[i];
            const bool pred = (lin_bin(v) == sel0);
            unsigned bal = __ballot_sync(0xFFFFFFFFu, pred);
            if (bal) {
                int base_ = 0;
                if (lane == 0) base_ = atomicAdd(&s_gcnt, __popc(bal));
                base_ = __shfl_sync(0xFFFFFFFFu, base_, 0);
                if (pred) buf[base_ + __popc(bal & ((1u << lane) - 1))] = __float_as_uint(v);
            }
        }
        __syncthreads();
        const int gcnt = s_gcnt;

        // exact refinement over the small candidate buffer: 3 bit-level stages
        unsigned prefix = 0;
        #pragma unroll
        for (int s = 0; s < 3; s++) {
            const int shift = (s == 0) ? 21 : (s == 1 ? 10 : 0);
            const int nbits = (s == 2) ? 10 : 11;
            const int bins  = 1 << nbits;
            const unsigned msk = bins - 1;
            const int gper  = bins >> 8;

            for (int i = tid; i < bins; i += SEL_T) hist[i] = 0u;
            __syncthreads();
            for (int i = tid; i < gcnt; i += SEL_T) {
                unsigned bits = buf[i];
                bool ok = (s == 0) || ((bits >> (shift + nbits)) == prefix);
                if (ok) atomicAdd(&hist[(bits >> shift) & msk], 1u);
            }
            __syncthreads();
            if (tid < 256) {
                unsigned t = 0;
                for (int j = 0; j < gper; j++) t += hist[tid * gper + j];
                gsum[tid] = t;
            }
            __syncthreads();
            if (tid < 32) warp_locate(hist, gsum, gper, k, &s_sel, &s_krem);
            __syncthreads();
            prefix = (prefix << nbits) | s_sel;
            k = (int)s_krem;
            __syncthreads();
        }
        tb   = prefix;
        ties = k;
    }

    const float tval = __uint_as_float(tb);

    // final: deterministic strided sum of strictly-above-threshold values
    float acc = 0.f;
    if (k0 > 0) {
        for (int i = tid; i < NN; i += SEL_T) {
            float v = vals[i];
            if (__float_as_uint(v) > tb) acc += v;
        }
    }
    #pragma unroll
    for (int o = 16; o; o >>= 1) acc += __shfl_down_sync(0xFFFFFFFFu, acc, o);
    const int w = tid >> 5;
    if (lane == 0) red[w] = acc;
    __syncthreads();
    if (tid == 0) {
        float negsum = 0.f;
        #pragma unroll
        for (int i = 0; i < 32; i++) negsum += red[i];
        negsum += (float)ties * tval;

        float lb = s_lossb;
        float ll = s_cepos + negsum;
        int   pn = s_pos;
        float nm = (pn > 0) ? 1.f : 0.f;
        float pf = fmaxf((float)pn, FP32_EPS);
        d_res[b * 3 + 0] = (lb + ll) * nm / pf;
        d_res[b * 3 + 1] = lb * nm / pf;
        d_res[b * 3 + 2] = ll * nm / pf;

        __threadfence();
        s_last = (atomicAdd(&d_done, 1) == BB - 1);
    }
    __syncthreads();

    // fused final reduction: last-finishing block reduces all 64 batch results
    if (s_last) {
        __threadfence();
        float lt = 0.f, vb = 0.f, vl = 0.f;
        if (tid < BB) {
            volatile float* r = d_res;
            lt = r[tid * 3 + 0];
            vb = r[tid * 3 + 1];
            vl = r[tid * 3 + 2];
        }
        if (tid < 64) {
            #pragma unroll
            for (int o = 16; o; o >>= 1) {
                lt += __shfl_down_sync(0xFFFFFFFFu, lt, o);
                vb += __shfl_down_sync(0xFFFFFFFFu, vb, o);
                vl += __shfl_down_sync(0xFFFFFFFFu, vl, o);
            }
            if ((tid & 31) == 0) {
                red[tid >> 5]       = lt;
                red[(tid >> 5) + 2] = vb;
                red[(tid >> 5) + 4] = vl;
            }
        }
        __syncthreads();
        if (tid == 0) {
            out[0] = (red[0] + red[1]) * (1.f / 64.f);
            out[1] = (red[2] + red[3]) * (1.f / 64.f);
            out[2] = (red[4] + red[5]) * (1.f / 64.f);
            d_done = 0;   // self-reset for next graph replay
        }
    }
}

// ---------------- launch ----------------
extern "C" void kernel_launch(void* const* d_in, const int* in_sizes, int n_in,
                              void* d_out, int out_size) {
    const float4* pb  = (const float4*)d_in[0];
    const float4* gb  = (const float4*)d_in[1];
    const float4* pl4 = (const float4*)d_in[2];
    const int*    gl  = (const int*)d_in[3];
    const float4* anc = (const float4*)d_in[4];
    float* out = (float*)d_out;

    static bool attr_set = false;
    if (!attr_set) {
        cudaFuncSetAttribute(k_select, cudaFuncAttributeMaxDynamicSharedMemorySize, SEL_SMEM);
        attr_set = true;
    }

    dim3 gBN(NBLK, BB);
    k_main<<<gBN, TPB>>>(pb, gb, pl4, gl, anc);
    k_select<<<BB, SEL_T, SEL_SMEM>>>(out);
}